// round 16
// baseline (speedup 1.0000x reference)
#include <cuda_runtime.h>

// DyDepthwiseConvAtten fused: dynamic 3-tap depthwise conv along C + LayerNorm.
// B*N = 102400 rows, C = 256. R15 = R14 body (packed contiguous-span layout,
// epilogue gamma/beta, grid 1184) with L2 prefetch DISTANCE 2: each iteration
// prefetches row + 2*stride (row+1*stride primed before the loop), giving
// ~2 iterations (~3k cyc) of lead time so demand LDGs land at L2-hit latency.
// Each row still prefetched exactly once; zero register cost.

#define C_DIM  256
#define LN_EPS 1e-5f
#define FULL   0xFFFFFFFFu

__device__ __forceinline__ void l2_prefetch(const void* p) {
    asm volatile("prefetch.global.L2 [%0];" :: "l"(p));
}

__global__ __launch_bounds__(256)
void dydwconv_ln_kernel(const float* __restrict__ q,
                        const float* __restrict__ v,
                        const float* __restrict__ Ww,     // [3,256]
                        const float* __restrict__ bw,     // [3]
                        const float* __restrict__ gamma,  // [256]
                        const float* __restrict__ beta,   // [256]
                        float* __restrict__ out,
                        int rows, int total_warps)
{
    const int warp_g = (blockIdx.x * blockDim.x + threadIdx.x) >> 5;
    const int lane   = threadIdx.x & 31;
    const int cA     = lane * 4;           // chunk A: channels [cA, cA+4)
    const int cB     = 128 + lane * 4;     // chunk B: channels [cB, cB+4)

    // ---- conv-weight rows hoisted to registers (hot FMA chain only) ----
    float W0[8], W1[8], W2[8];
    {
        float4 a, b;
        a = *(const float4*)(Ww + 0 * C_DIM + cA);  b = *(const float4*)(Ww + 0 * C_DIM + cB);
        W0[0]=a.x; W0[1]=a.y; W0[2]=a.z; W0[3]=a.w; W0[4]=b.x; W0[5]=b.y; W0[6]=b.z; W0[7]=b.w;
        a = *(const float4*)(Ww + 1 * C_DIM + cA);  b = *(const float4*)(Ww + 1 * C_DIM + cB);
        W1[0]=a.x; W1[1]=a.y; W1[2]=a.z; W1[3]=a.w; W1[4]=b.x; W1[5]=b.y; W1[6]=b.z; W1[7]=b.w;
        a = *(const float4*)(Ww + 2 * C_DIM + cA);  b = *(const float4*)(Ww + 2 * C_DIM + cB);
        W2[0]=a.x; W2[1]=a.y; W2[2]=a.z; W2[3]=a.w; W2[4]=b.x; W2[5]=b.y; W2[6]=b.z; W2[7]=b.w;
    }
    const float bw0 = bw[0], bw1 = bw[1], bw2 = bw[2];

    // ---- prime the pipeline: prefetch row + 1*stride ----
    {
        const int prow = warp_g + total_warps;
        if (prow < rows) {
            const size_t pbase = (size_t)prow * C_DIM;
            l2_prefetch(q + pbase + cA);
            l2_prefetch(q + pbase + cB);
            l2_prefetch(v + pbase + cA);
            l2_prefetch(v + pbase + cB);
        }
    }

    for (int row = warp_g; row < rows; row += total_warps) {
        const size_t rbase = (size_t)row * C_DIM;

        // ---- L2 prefetch, distance 2 (clamped; 0 registers) ----
        {
            const int nrow = row + 2 * total_warps;
            const int crow = nrow < rows ? nrow : row;
            const size_t nbase = (size_t)crow * C_DIM;
            l2_prefetch(q + nbase + cA);
            l2_prefetch(q + nbase + cB);
            l2_prefetch(v + nbase + cA);
            l2_prefetch(v + nbase + cB);
        }

        // ---- 4 contiguous-span LDG.128 (512B warp span each) ----
        const float4 qa = *(const float4*)(q + rbase + cA);
        const float4 qb = *(const float4*)(q + rbase + cB);
        const float4 va = *(const float4*)(v + rbase + cA);
        const float4 vb = *(const float4*)(v + rbase + cB);

        float Q[8] = {qa.x, qa.y, qa.z, qa.w, qb.x, qb.y, qb.z, qb.w};
        float V[8] = {va.x, va.y, va.z, va.w, vb.x, vb.y, vb.z, vb.w};

        // ---- dynamic kernel weights: w_k = bw[k] + sum_c q[c]*Ww[k][c] ----
        float p0 = 0.f, p1 = 0.f, p2 = 0.f;
        #pragma unroll
        for (int i = 0; i < 8; i++) {
            p0 = fmaf(Q[i], W0[i], p0);
            p1 = fmaf(Q[i], W1[i], p1);
            p2 = fmaf(Q[i], W2[i], p2);
        }
        #pragma unroll
        for (int off = 16; off > 0; off >>= 1) {
            p0 += __shfl_xor_sync(FULL, p0, off);
            p1 += __shfl_xor_sync(FULL, p1, off);
            p2 += __shfl_xor_sync(FULL, p2, off);
        }
        const float w0 = bw0 + p0;
        const float w1 = bw1 + p1;
        const float w2 = bw2 + p2;

        // ---- halo exchange, packed layout (zero padded at c=0 / c=255) ----
        float vAl = __shfl_up_sync(FULL, V[3], 1);     // v[4L-1]
        float vBl = __shfl_up_sync(FULL, V[7], 1);     // v[128+4L-1]
        float vAr = __shfl_down_sync(FULL, V[0], 1);   // v[4L+4]
        float vBr = __shfl_down_sync(FULL, V[4], 1);   // v[128+4L+4]
        const float v127 = __shfl_sync(FULL, V[3], 31);
        const float v128 = __shfl_sync(FULL, V[4], 0);
        if (lane == 0)  { vAl = 0.f;  vBl = v127; }
        if (lane == 31) { vAr = v128; vBr = 0.f; }

        // ---- 3-tap conv per chunk + LN partials ----
        float O[8];
        O[0] = vAl  * w0 + V[0] * w1 + V[1] * w2;
        O[1] = V[0] * w0 + V[1] * w1 + V[2] * w2;
        O[2] = V[1] * w0 + V[2] * w1 + V[3] * w2;
        O[3] = V[2] * w0 + V[3] * w1 + vAr  * w2;
        O[4] = vBl  * w0 + V[4] * w1 + V[5] * w2;
        O[5] = V[4] * w0 + V[5] * w1 + V[6] * w2;
        O[6] = V[5] * w0 + V[6] * w1 + V[7] * w2;
        O[7] = V[6] * w0 + V[7] * w1 + vBr  * w2;

        float s = 0.f, ss = 0.f;
        #pragma unroll
        for (int i = 0; i < 8; i++) {
            s += O[i];
            ss = fmaf(O[i], O[i], ss);
        }
        #pragma unroll
        for (int off = 16; off > 0; off >>= 1) {
            s  += __shfl_xor_sync(FULL, s,  off);
            ss += __shfl_xor_sync(FULL, ss, off);
        }
        const float mean = s  * (1.0f / C_DIM);
        const float var  = ss * (1.0f / C_DIM) - mean * mean;
        const float inv  = rsqrtf(var + LN_EPS);

        // ---- gamma/beta loaded here (L2-resident 768B, off critical path) ----
        const float4 ga = __ldg((const float4*)(gamma + cA));
        const float4 gb = __ldg((const float4*)(gamma + cB));
        const float4 ba = __ldg((const float4*)(beta  + cA));
        const float4 bb = __ldg((const float4*)(beta  + cB));

        float4 oa, ob;
        oa.x = (O[0] - mean) * inv * ga.x + ba.x;
        oa.y = (O[1] - mean) * inv * ga.y + ba.y;
        oa.z = (O[2] - mean) * inv * ga.z + ba.z;
        oa.w = (O[3] - mean) * inv * ga.w + ba.w;
        ob.x = (O[4] - mean) * inv * gb.x + bb.x;
        ob.y = (O[5] - mean) * inv * gb.y + bb.y;
        ob.z = (O[6] - mean) * inv * gb.z + bb.z;
        ob.w = (O[7] - mean) * inv * gb.w + bb.w;
        *(float4*)(out + rbase + cA) = oa;
        *(float4*)(out + rbase + cB) = ob;
    }
}

extern "C" void kernel_launch(void* const* d_in, const int* in_sizes, int n_in,
                              void* d_out, int out_size)
{
    const float* q     = (const float*)d_in[0];
    const float* v     = (const float*)d_in[1];
    const float* Ww    = (const float*)d_in[2];
    const float* bw    = (const float*)d_in[3];
    const float* gamma = (const float*)d_in[4];
    const float* beta  = (const float*)d_in[5];
    float* out = (float*)d_out;

    const int rows = in_sizes[0] / C_DIM;        // 102400
    const int grid = 1184;                       // 148 SMs * 8 CTAs
    const int total_warps = grid * (256 / 32);   // 9472
    dydwconv_ln_kernel<<<grid, 256>>>(q, v, Ww, bw, gamma, beta, out,
                                      rows, total_warps);
}

// round 17
// speedup vs baseline: 1.1546x; 1.1546x over previous
#include <cuda_runtime.h>

// DyDepthwiseConvAtten fused: dynamic 3-tap depthwise conv along C + LayerNorm.
// B*N = 102400 rows, C = 256. R16 = R14 champion body (packed contiguous-span
// layout: lane L owns channels [4L,4L+4) and [128+4L,..+4); distance-1 L2
// prefetch; epilogue gamma/beta; grid 1184) with ONE reorder: demand LDG.128s
// issue FIRST, prefetches follow — demand MLP establishes immediately and the
// prefetches fill the scoreboard-wait window. (R15's distance-2 variant
// regressed 8us by perturbing the compiled issue schedule; reverted.)

#define C_DIM  256
#define LN_EPS 1e-5f
#define FULL   0xFFFFFFFFu

__device__ __forceinline__ void l2_prefetch(const void* p) {
    asm volatile("prefetch.global.L2 [%0];" :: "l"(p));
}

__global__ __launch_bounds__(256)
void dydwconv_ln_kernel(const float* __restrict__ q,
                        const float* __restrict__ v,
                        const float* __restrict__ Ww,     // [3,256]
                        const float* __restrict__ bw,     // [3]
                        const float* __restrict__ gamma,  // [256]
                        const float* __restrict__ beta,   // [256]
                        float* __restrict__ out,
                        int rows, int total_warps)
{
    const int warp_g = (blockIdx.x * blockDim.x + threadIdx.x) >> 5;
    const int lane   = threadIdx.x & 31;
    const int cA     = lane * 4;           // chunk A: channels [cA, cA+4)
    const int cB     = 128 + lane * 4;     // chunk B: channels [cB, cB+4)

    // ---- conv-weight rows hoisted to registers (hot FMA chain only) ----
    float W0[8], W1[8], W2[8];
    {
        float4 a, b;
        a = *(const float4*)(Ww + 0 * C_DIM + cA);  b = *(const float4*)(Ww + 0 * C_DIM + cB);
        W0[0]=a.x; W0[1]=a.y; W0[2]=a.z; W0[3]=a.w; W0[4]=b.x; W0[5]=b.y; W0[6]=b.z; W0[7]=b.w;
        a = *(const float4*)(Ww + 1 * C_DIM + cA);  b = *(const float4*)(Ww + 1 * C_DIM + cB);
        W1[0]=a.x; W1[1]=a.y; W1[2]=a.z; W1[3]=a.w; W1[4]=b.x; W1[5]=b.y; W1[6]=b.z; W1[7]=b.w;
        a = *(const float4*)(Ww + 2 * C_DIM + cA);  b = *(const float4*)(Ww + 2 * C_DIM + cB);
        W2[0]=a.x; W2[1]=a.y; W2[2]=a.z; W2[3]=a.w; W2[4]=b.x; W2[5]=b.y; W2[6]=b.z; W2[7]=b.w;
    }
    const float bw0 = bw[0], bw1 = bw[1], bw2 = bw[2];

    for (int row = warp_g; row < rows; row += total_warps) {
        const size_t rbase = (size_t)row * C_DIM;

        // ---- 4 contiguous-span demand LDG.128 first (512B warp span each) ----
        const float4 qa = *(const float4*)(q + rbase + cA);
        const float4 qb = *(const float4*)(q + rbase + cB);
        const float4 va = *(const float4*)(v + rbase + cA);
        const float4 vb = *(const float4*)(v + rbase + cB);

        // ---- then L2 prefetch of next grid-stride row (clamped; 0 regs) ----
        {
            const int nrow = row + total_warps;
            const int crow = nrow < rows ? nrow : row;
            const size_t nbase = (size_t)crow * C_DIM;
            l2_prefetch(q + nbase + cA);
            l2_prefetch(q + nbase + cB);
            l2_prefetch(v + nbase + cA);
            l2_prefetch(v + nbase + cB);
        }

        float Q[8] = {qa.x, qa.y, qa.z, qa.w, qb.x, qb.y, qb.z, qb.w};
        float V[8] = {va.x, va.y, va.z, va.w, vb.x, vb.y, vb.z, vb.w};

        // ---- dynamic kernel weights: w_k = bw[k] + sum_c q[c]*Ww[k][c] ----
        float p0 = 0.f, p1 = 0.f, p2 = 0.f;
        #pragma unroll
        for (int i = 0; i < 8; i++) {
            p0 = fmaf(Q[i], W0[i], p0);
            p1 = fmaf(Q[i], W1[i], p1);
            p2 = fmaf(Q[i], W2[i], p2);
        }
        #pragma unroll
        for (int off = 16; off > 0; off >>= 1) {
            p0 += __shfl_xor_sync(FULL, p0, off);
            p1 += __shfl_xor_sync(FULL, p1, off);
            p2 += __shfl_xor_sync(FULL, p2, off);
        }
        const float w0 = bw0 + p0;
        const float w1 = bw1 + p1;
        const float w2 = bw2 + p2;

        // ---- halo exchange, packed layout (zero padded at c=0 / c=255) ----
        float vAl = __shfl_up_sync(FULL, V[3], 1);     // v[4L-1]
        float vBl = __shfl_up_sync(FULL, V[7], 1);     // v[128+4L-1]
        float vAr = __shfl_down_sync(FULL, V[0], 1);   // v[4L+4]
        float vBr = __shfl_down_sync(FULL, V[4], 1);   // v[128+4L+4]
        const float v127 = __shfl_sync(FULL, V[3], 31);
        const float v128 = __shfl_sync(FULL, V[4], 0);
        if (lane == 0)  { vAl = 0.f;  vBl = v127; }
        if (lane == 31) { vAr = v128; vBr = 0.f; }

        // ---- 3-tap conv per chunk + LN partials ----
        float O[8];
        O[0] = vAl  * w0 + V[0] * w1 + V[1] * w2;
        O[1] = V[0] * w0 + V[1] * w1 + V[2] * w2;
        O[2] = V[1] * w0 + V[2] * w1 + V[3] * w2;
        O[3] = V[2] * w0 + V[3] * w1 + vAr  * w2;
        O[4] = vBl  * w0 + V[4] * w1 + V[5] * w2;
        O[5] = V[4] * w0 + V[5] * w1 + V[6] * w2;
        O[6] = V[5] * w0 + V[6] * w1 + V[7] * w2;
        O[7] = V[6] * w0 + V[7] * w1 + vBr  * w2;

        float s = 0.f, ss = 0.f;
        #pragma unroll
        for (int i = 0; i < 8; i++) {
            s += O[i];
            ss = fmaf(O[i], O[i], ss);
        }
        #pragma unroll
        for (int off = 16; off > 0; off >>= 1) {
            s  += __shfl_xor_sync(FULL, s,  off);
            ss += __shfl_xor_sync(FULL, ss, off);
        }
        const float mean = s  * (1.0f / C_DIM);
        const float var  = ss * (1.0f / C_DIM) - mean * mean;
        const float inv  = rsqrtf(var + LN_EPS);

        // ---- gamma/beta loaded here (L2-resident 768B, off critical path) ----
        const float4 ga = __ldg((const float4*)(gamma + cA));
        const float4 gb = __ldg((const float4*)(gamma + cB));
        const float4 ba = __ldg((const float4*)(beta  + cA));
        const float4 bb = __ldg((const float4*)(beta  + cB));

        float4 oa, ob;
        oa.x = (O[0] - mean) * inv * ga.x + ba.x;
        oa.y = (O[1] - mean) * inv * ga.y + ba.y;
        oa.z = (O[2] - mean) * inv * ga.z + ba.z;
        oa.w = (O[3] - mean) * inv * ga.w + ba.w;
        ob.x = (O[4] - mean) * inv * gb.x + bb.x;
        ob.y = (O[5] - mean) * inv * gb.y + bb.y;
        ob.z = (O[6] - mean) * inv * gb.z + bb.z;
        ob.w = (O[7] - mean) * inv * gb.w + bb.w;
        *(float4*)(out + rbase + cA) = oa;
        *(float4*)(out + rbase + cB) = ob;
    }
}

extern "C" void kernel_launch(void* const* d_in, const int* in_sizes, int n_in,
                              void* d_out, int out_size)
{
    const float* q     = (const float*)d_in[0];
    const float* v     = (const float*)d_in[1];
    const float* Ww    = (const float*)d_in[2];
    const float* bw    = (const float*)d_in[3];
    const float* gamma = (const float*)d_in[4];
    const float* beta  = (const float*)d_in[5];
    float* out = (float*)d_out;

    const int rows = in_sizes[0] / C_DIM;        // 102400
    const int grid = 1184;                       // 148 SMs * 8 CTAs
    const int total_warps = grid * (256 / 32);   // 9472
    dydwconv_ln_kernel<<<grid, 256>>>(q, v, Ww, bw, gamma, beta, out,
                                      rows, total_warps);
}